// round 14
// baseline (speedup 1.0000x reference)
#include <cuda_runtime.h>
#include <cuda_bf16.h>
#include <cstdint>
#include <math.h>

// ---------------- problem constants ----------------
#define BATCH     2
#define HW        128
#define LQ        (HW*HW)          // 16384
#define N_LEVELS  4
#define LIN       (N_LEVELS*LQ)    // 65536
#define D_MODEL   256
#define N_HEADS   8
#define HEAD_DIM  32
#define N_POINTS  4
#define D_FFN     1024
#define LN_EPS    1e-5f

#define M_Q   (BATCH*LQ)           // 32768
#define M_V   (BATCH*LIN)          // 131072

// ---------------- scratch layout (in floats) ----------------
#define OFF_VALUEB  0            // value bf16           M_V*256
#define OFF_QB      16777216     // q bf16               M_Q*256
#define OFF_OFFB    20971520     // off fp32             M_Q*256
#define OFF_ATTN    29360128     // attn fp32            M_Q*128
#define OFF_AOB     33554432     // attnout bf16         M_Q*256
#define OFF_SRC     37748736     // src fp32             M_Q*256
#define OFF_SRCB    46137344     // src bf16             M_Q*256
#define OFF_HB      50331648     // h bf16               M_Q*1024
#define OFF_WVH     67108864
#define OFF_WVL     67141632
#define OFF_WOH     67174400
#define OFF_WOL     67207168
#define OFF_WAH     67239936
#define OFF_WAL     67256320
#define OFF_WUH     67272704
#define OFF_WUL     67305472
#define OFF_W1H     67338240
#define OFF_W1L     67469312
#define OFF_W2H     67600384
#define OFF_W2L     67731456
#define SCRATCH_FLOATS 67862528

__device__ float g_scratch[SCRATCH_FLOATS];

// ---------------- helpers ----------------
__device__ __forceinline__ uint32_t smem_u32(const void* p) {
    uint32_t a;
    asm("{ .reg .u64 t; cvta.to.shared.u64 t, %1; cvt.u32.u64 %0, t; }" : "=r"(a) : "l"(p));
    return a;
}

__device__ __forceinline__ unsigned short b16(float x) {
    return __bfloat16_as_ushort(__float2bfloat16_rn(x));
}

__device__ __forceinline__ void ldm_x4(uint32_t* r, uint32_t addr) {
    asm volatile("ldmatrix.sync.aligned.m8n8.x4.shared.b16 {%0,%1,%2,%3}, [%4];"
        : "=r"(r[0]), "=r"(r[1]), "=r"(r[2]), "=r"(r[3]) : "r"(addr));
}

__device__ __forceinline__ void mma_bf16(float* c, const uint32_t* a, const uint32_t* b) {
    asm volatile(
        "mma.sync.aligned.m16n8k16.row.col.f32.bf16.bf16.f32 "
        "{%0,%1,%2,%3}, {%4,%5,%6,%7}, {%8,%9}, {%0,%1,%2,%3};"
        : "+f"(c[0]), "+f"(c[1]), "+f"(c[2]), "+f"(c[3])
        : "r"(a[0]), "r"(a[1]), "r"(a[2]), "r"(a[3]), "r"(b[0]), "r"(b[1]));
}

__device__ __forceinline__ void cp16(uint32_t dst, const void* src) {
    asm volatile("cp.async.cg.shared.global [%0], [%1], 16;" :: "r"(dst), "l"(src));
}
__device__ __forceinline__ void cp_commit() { asm volatile("cp.async.commit_group;"); }
template<int W> __device__ __forceinline__ void cp_wait() {
    asm volatile("cp.async.wait_group %0;" :: "n"(W));
}

#define SMPAD 40
#define MATW  (128 * SMPAD)

// ---------------- merged weight transpose + bf16 hi/lo split ----------------
struct WSJobs {
    const float* src[6];
    __nv_bfloat16* hi[6];
    __nv_bfloat16* lo[6];
    int K[6];
    int N[6];
    int off[7];
};

__global__ void wsplit_all_kernel(WSJobs jobs)
{
    int idx = blockIdx.x * blockDim.x + threadIdx.x;
    if (idx >= jobs.off[6]) return;
    #pragma unroll
    for (int s = 0; s < 6; s++) {
        if (idx >= jobs.off[s] && idx < jobs.off[s + 1]) {
            int local = idx - jobs.off[s];
            int N = jobs.N[s], K = jobs.K[s];
            int k = local / N, n = local - k * N;
            float x = jobs.src[s][local];
            __nv_bfloat16 h = __float2bfloat16_rn(x);
            __nv_bfloat16 l = __float2bfloat16_rn(x - __bfloat162float(h));
            jobs.hi[s][(size_t)n * K + k] = h;
            jobs.lo[s][(size_t)n * K + k] = l;
            return;
        }
    }
}

// ---------------- q = cur + pos[:,3] -> single bf16 ----------------
__global__ void q_cvt_kernel(const float* __restrict__ cur, const float* __restrict__ pos,
                             __nv_bfloat16* __restrict__ o, int total4)
{
    int i = blockIdx.x * blockDim.x + threadIdx.x;
    if (i >= total4) return;
    int idx = i * 4;
    int n = idx / (LQ * D_MODEL);
    int rem = idx - n * (LQ * D_MODEL);
    float4 va = *(const float4*)(cur + idx);
    float4 vb = *(const float4*)(pos + (size_t)(n * N_LEVELS + 3) * (LQ * D_MODEL) + rem);
    uint2 hp;
    hp.x = ((uint32_t)b16(va.y + vb.y) << 16) | b16(va.x + vb.x);
    hp.y = ((uint32_t)b16(va.w + vb.w) << 16) | b16(va.z + vb.z);
    ((uint2*)o)[i] = hp;
}

// ---------------- bf16 HMMA GEMM (optional B hi/lo split) ----------------
// CTA tile 128x128, BK=32, double-buffered cp.async, 8 warps (4m x 2n).
// EPI: 0=none 1=relu 3=softmax16.  OMODE: 0=fp32 C, 1=bf16 Cb.
template<int EPI, int OMODE, int BSPLIT>
__global__ void __launch_bounds__(256, 2) gemm2(
    const __nv_bfloat16* __restrict__ A,
    const __nv_bfloat16* __restrict__ Bhi, const __nv_bfloat16* __restrict__ Blo,
    const float* __restrict__ bias,
    float* __restrict__ C, __nv_bfloat16* __restrict__ Cb,
    int M, int N, int K)
{
    const int NMAT = BSPLIT ? 3 : 2;
    extern __shared__ unsigned short sm[];
    const int tid = threadIdx.x;
    const int wid = tid >> 5, lane = tid & 31;
    const int wm = wid & 3, wn = wid >> 2;
    const int m0 = blockIdx.y * 128, n0 = blockIdx.x * 128;
    const uint32_t smb = smem_u32(sm);

    const int a_r  = lane & 15;
    const int a_kb = (lane >> 4) * 16;
    const int b_r  = ((lane >> 4) & 1) * 8 + (lane & 7);
    const int b_kb = ((lane >> 3) & 1) * 16;

    const int row_l = tid >> 2;
    const int q4    = tid & 3;

    float acc[2][8][4];
    #pragma unroll
    for (int i = 0; i < 2; i++)
        #pragma unroll
        for (int j = 0; j < 8; j++)
            #pragma unroll
            for (int t = 0; t < 4; t++) acc[i][j][t] = 0.f;

    const int nchunks = K >> 5;

    auto stage_load = [&](int buf, int k0) {
        #pragma unroll
        for (int j = 0; j < 2 * NMAT; j++) {
            const int mat = j >> 1;
            const int row = (j & 1) * 64 + row_l;
            const __nv_bfloat16* base = (mat == 0) ? A : (mat == 1) ? Bhi : Blo;
            const int r0 = (mat == 0) ? m0 : n0;
            const __nv_bfloat16* src = base + (size_t)(r0 + row) * K + k0 + q4 * 8;
            const uint32_t dst = smb +
                (uint32_t)(((buf * NMAT + mat) * MATW + row * SMPAD + q4 * 8) * 2);
            cp16(dst, src);
        }
        cp_commit();
    };

    stage_load(0, 0);
    for (int i = 0; i < nchunks; i++) {
        if (i + 1 < nchunks) { stage_load((i + 1) & 1, (i + 1) << 5); cp_wait<1>(); }
        else                 { cp_wait<0>(); }
        __syncthreads();

        const uint32_t sb  = smb + (uint32_t)((i & 1) * NMAT * MATW * 2);
        const uint32_t AB  = sb;
        const uint32_t BhB = sb + MATW * 2, BlB = sb + 2 * MATW * 2;

        #pragma unroll
        for (int ks2 = 0; ks2 <= 32; ks2 += 32) {
            uint32_t ar[2][4];
            #pragma unroll
            for (int mi = 0; mi < 2; mi++) {
                const uint32_t ao = (uint32_t)((wm * 32 + mi * 16 + a_r) * (SMPAD * 2)) + a_kb + ks2;
                ldm_x4(ar[mi], AB + ao);
            }
            #pragma unroll
            for (int nc = 0; nc < 4; nc++) {
                uint32_t bh[4], bl[4];
                const uint32_t bo = (uint32_t)((wn * 64 + nc * 16 + b_r) * (SMPAD * 2)) + b_kb + ks2;
                ldm_x4(bh, BhB + bo);
                if (BSPLIT) ldm_x4(bl, BlB + bo);
                #pragma unroll
                for (int mi = 0; mi < 2; mi++) {
                    #pragma unroll
                    for (int s = 0; s < 2; s++) {
                        float* c = acc[mi][nc * 2 + s];
                        mma_bf16(c, ar[mi], bh + s * 2);
                        if (BSPLIT) mma_bf16(c, ar[mi], bl + s * 2);
                    }
                }
            }
        }
        __syncthreads();
    }

    const int gr = lane >> 2, gc = (lane & 3) * 2;

    if (EPI == 3) {
        #pragma unroll
        for (int mi = 0; mi < 2; mi++) {
            #pragma unroll
            for (int hrow = 0; hrow < 2; hrow++) {
                const int row = m0 + wm * 32 + mi * 16 + gr + hrow * 8;
                #pragma unroll
                for (int g = 0; g < 4; g++) {
                    const int c0 = n0 + wn * 64 + g * 16;
                    float a0 = acc[mi][2*g  ][2*hrow + 0] + bias[c0 + gc];
                    float a1 = acc[mi][2*g  ][2*hrow + 1] + bias[c0 + gc + 1];
                    float b0 = acc[mi][2*g+1][2*hrow + 0] + bias[c0 + 8 + gc];
                    float b1 = acc[mi][2*g+1][2*hrow + 1] + bias[c0 + 8 + gc + 1];
                    float mx = fmaxf(fmaxf(a0, a1), fmaxf(b0, b1));
                    mx = fmaxf(mx, __shfl_xor_sync(0xffffffffu, mx, 1));
                    mx = fmaxf(mx, __shfl_xor_sync(0xffffffffu, mx, 2));
                    a0 = __expf(a0 - mx); a1 = __expf(a1 - mx);
                    b0 = __expf(b0 - mx); b1 = __expf(b1 - mx);
                    float s = a0 + a1 + b0 + b1;
                    s += __shfl_xor_sync(0xffffffffu, s, 1);
                    s += __shfl_xor_sync(0xffffffffu, s, 2);
                    const float inv = 1.f / s;
                    *(float2*)(C + (size_t)row * N + c0 + gc)     = make_float2(a0 * inv, a1 * inv);
                    *(float2*)(C + (size_t)row * N + c0 + 8 + gc) = make_float2(b0 * inv, b1 * inv);
                }
            }
        }
        return;
    }

    #pragma unroll
    for (int mi = 0; mi < 2; mi++) {
        const int row = m0 + wm * 32 + mi * 16 + gr;
        #pragma unroll
        for (int ni = 0; ni < 8; ni++) {
            const int col = n0 + wn * 64 + ni * 8 + gc;
            const float b0 = bias[col], b1 = bias[col + 1];
            float2 v0, v1;
            v0.x = acc[mi][ni][0] + b0; v0.y = acc[mi][ni][1] + b1;
            v1.x = acc[mi][ni][2] + b0; v1.y = acc[mi][ni][3] + b1;
            if (EPI == 1) {
                v0.x = fmaxf(v0.x, 0.f); v0.y = fmaxf(v0.y, 0.f);
                v1.x = fmaxf(v1.x, 0.f); v1.y = fmaxf(v1.y, 0.f);
            }
            if (OMODE == 1) {
                *(uint32_t*)(Cb + (size_t)row * N + col) =
                    ((uint32_t)b16(v0.y) << 16) | b16(v0.x);
                *(uint32_t*)(Cb + (size_t)(row + 8) * N + col) =
                    ((uint32_t)b16(v1.y) << 16) | b16(v1.x);
            } else {
                *(float2*)(C + (size_t)row * N + col) = v0;
                *(float2*)(C + (size_t)(row + 8) * N + col) = v1;
            }
        }
    }
}

// ---------------- value GEMM with fused (a+b) fp32 -> bf16 A-staging ----------------
// C_bf16 = (Af1+Af2) @ B^T + bias; B single bf16 cp.async double-buffered,
// A staged synchronously (fill for chunk i+1 issued before compute(i)).
__global__ void __launch_bounds__(256, 2) gemm_va(
    const float* __restrict__ Af1, const float* __restrict__ Af2,
    const __nv_bfloat16* __restrict__ B,
    const float* __restrict__ bias, __nv_bfloat16* __restrict__ Cb,
    int M, int N, int K)
{
    extern __shared__ unsigned short sm[];
    const int tid = threadIdx.x;
    const int wid = tid >> 5, lane = tid & 31;
    const int wm = wid & 3, wn = wid >> 2;
    const int m0 = blockIdx.y * 128, n0 = blockIdx.x * 128;
    const uint32_t smb = smem_u32(sm);

    const int a_r  = lane & 15;
    const int a_kb = (lane >> 4) * 16;
    const int b_r  = ((lane >> 4) & 1) * 8 + (lane & 7);
    const int b_kb = ((lane >> 3) & 1) * 16;

    const int row_l = tid >> 2;
    const int q4    = tid & 3;
    const int fr    = tid >> 1;          // 0..127 (A fill row)
    const int fh    = tid & 1;           // col half

    float acc[2][8][4];
    #pragma unroll
    for (int i = 0; i < 2; i++)
        #pragma unroll
        for (int j = 0; j < 8; j++)
            #pragma unroll
            for (int t = 0; t < 4; t++) acc[i][j][t] = 0.f;

    const int nchunks = K >> 5;

    auto fillA = [&](int buf, int k0) {
        const float* p1 = Af1 + (size_t)(m0 + fr) * K + k0 + fh * 16;
        const float* p2 = Af2 + (size_t)(m0 + fr) * K + k0 + fh * 16;
        unsigned short* dst = sm + (size_t)buf * 2 * MATW + fr * SMPAD + fh * 16;
        #pragma unroll
        for (int i = 0; i < 4; i++) {
            float4 a = *(const float4*)(p1 + i * 4);
            float4 b = *(const float4*)(p2 + i * 4);
            uint2 pk;
            pk.x = ((uint32_t)b16(a.y + b.y) << 16) | b16(a.x + b.x);
            pk.y = ((uint32_t)b16(a.w + b.w) << 16) | b16(a.z + b.z);
            *(uint2*)(dst + i * 4) = pk;
        }
    };
    auto cpB = [&](int buf, int k0) {
        #pragma unroll
        for (int j = 0; j < 2; j++) {
            const int row = j * 64 + row_l;
            const __nv_bfloat16* src = B + (size_t)(n0 + row) * K + k0 + q4 * 8;
            const uint32_t dst = smb +
                (uint32_t)(((buf * 2 + 1) * MATW + row * SMPAD + q4 * 8) * 2);
            cp16(dst, src);
        }
        cp_commit();
    };

    fillA(0, 0);
    cpB(0, 0);
    for (int i = 0; i < nchunks; i++) {
        if (i + 1 < nchunks) { cpB((i + 1) & 1, (i + 1) << 5); cp_wait<1>(); }
        else                 { cp_wait<0>(); }
        __syncthreads();
        if (i + 1 < nchunks) fillA((i + 1) & 1, (i + 1) << 5);

        const uint32_t sb  = smb + (uint32_t)((i & 1) * 2 * MATW * 2);
        const uint32_t AB  = sb;
        const uint32_t BhB = sb + MATW * 2;

        #pragma unroll
        for (int ks2 = 0; ks2 <= 32; ks2 += 32) {
            uint32_t ar[2][4];
            #pragma unroll
            for (int mi = 0; mi < 2; mi++) {
                const uint32_t ao = (uint32_t)((wm * 32 + mi * 16 + a_r) * (SMPAD * 2)) + a_kb + ks2;
                ldm_x4(ar[mi], AB + ao);
            }
            #pragma unroll
            for (int nc = 0; nc < 4; nc++) {
                uint32_t bh[4];
                const uint32_t bo = (uint32_t)((wn * 64 + nc * 16 + b_r) * (SMPAD * 2)) + b_kb + ks2;
                ldm_x4(bh, BhB + bo);
                #pragma unroll
                for (int mi = 0; mi < 2; mi++) {
                    #pragma unroll
                    for (int s = 0; s < 2; s++)
                        mma_bf16(acc[mi][nc * 2 + s], ar[mi], bh + s * 2);
                }
            }
        }
        __syncthreads();
    }

    const int gr = lane >> 2, gc = (lane & 3) * 2;
    #pragma unroll
    for (int mi = 0; mi < 2; mi++) {
        const int row = m0 + wm * 32 + mi * 16 + gr;
        #pragma unroll
        for (int ni = 0; ni < 8; ni++) {
            const int col = n0 + wn * 64 + ni * 8 + gc;
            const float b0 = bias[col], b1 = bias[col + 1];
            *(uint32_t*)(Cb + (size_t)row * N + col) =
                ((uint32_t)b16(acc[mi][ni][1] + b1) << 16) | b16(acc[mi][ni][0] + b0);
            *(uint32_t*)(Cb + (size_t)(row + 8) * N + col) =
                ((uint32_t)b16(acc[mi][ni][3] + b1) << 16) | b16(acc[mi][ni][2] + b0);
        }
    }
}

// ---------------- GEMM with fused bias+residual+LayerNorm epilogue ----------------
// BM=64, BN=256(=N), BK=32; 8 warps as 2m x 4n (warp tile 32x64).
// Y = LN(A @ B^T + bias + R); optional bf16 copy Yb.
#define LN_STAGE_ROWS 320
#define LN_STAGE_W   (LN_STAGE_ROWS * SMPAD)

template<bool OB>
__global__ void __launch_bounds__(256, 2) gemm_ln(
    const __nv_bfloat16* __restrict__ A, const __nv_bfloat16* __restrict__ B,
    const float* __restrict__ bias, const float* __restrict__ R,
    const float* __restrict__ gamma, const float* __restrict__ beta,
    float* __restrict__ Y, __nv_bfloat16* __restrict__ Yb,
    int M, int K)
{
    const int N = 256;
    extern __shared__ unsigned short sm[];
    const int tid = threadIdx.x;
    const int wid = tid >> 5, lane = tid & 31;
    const int wm = wid & 1, wn = wid >> 1;        // 2m x 4n
    const int m0 = blockIdx.x * 64;
    const uint32_t smb = smem_u32(sm);

    const int a_r  = lane & 15;
    const int a_kb = (lane >> 4) * 16;
    const int b_r  = ((lane >> 4) & 1) * 8 + (lane & 7);
    const int b_kb = ((lane >> 3) & 1) * 16;

    float acc[2][8][4];
    #pragma unroll
    for (int i = 0; i < 2; i++)
        #pragma unroll
        for (int j = 0; j < 8; j++)
            #pragma unroll
            for (int t = 0; t < 4; t++) acc[i][j][t] = 0.f;

    const int nchunks = K >> 5;

    auto stage_load = [&](int buf, int k0) {
        #pragma unroll
        for (int j = 0; j < 5; j++) {
            const int c = tid + j * 256;          // 0..1279
            const int row = c >> 2, q4c = c & 3;
            const __nv_bfloat16* src = (row < 64)
                ? A + (size_t)(m0 + row) * K + k0 + q4c * 8
                : B + (size_t)(row - 64) * K + k0 + q4c * 8;
            const uint32_t dst = smb +
                (uint32_t)((buf * LN_STAGE_W + row * SMPAD + q4c * 8) * 2);
            cp16(dst, src);
        }
        cp_commit();
    };

    stage_load(0, 0);
    for (int i = 0; i < nchunks; i++) {
        if (i + 1 < nchunks) { stage_load((i + 1) & 1, (i + 1) << 5); cp_wait<1>(); }
        else                 { cp_wait<0>(); }
        __syncthreads();

        const uint32_t sb = smb + (uint32_t)((i & 1) * LN_STAGE_W * 2);
        const uint32_t AB = sb;
        const uint32_t BB = sb + 64 * SMPAD * 2;

        #pragma unroll
        for (int ks2 = 0; ks2 <= 32; ks2 += 32) {
            uint32_t ar[2][4];
            #pragma unroll
            for (int mi = 0; mi < 2; mi++) {
                const uint32_t ao = (uint32_t)((wm * 32 + mi * 16 + a_r) * (SMPAD * 2)) + a_kb + ks2;
                ldm_x4(ar[mi], AB + ao);
            }
            #pragma unroll
            for (int nc = 0; nc < 4; nc++) {
                uint32_t bh[4];
                const uint32_t bo = (uint32_t)((wn * 64 + nc * 16 + b_r) * (SMPAD * 2)) + b_kb + ks2;
                ldm_x4(bh, BB + bo);
                #pragma unroll
                for (int mi = 0; mi < 2; mi++) {
                    #pragma unroll
                    for (int s = 0; s < 2; s++)
                        mma_bf16(acc[mi][nc * 2 + s], ar[mi], bh + s * 2);
                }
            }
        }
        __syncthreads();
    }

    // ---- fused bias + residual + LayerNorm epilogue ----
    const int gr = lane >> 2, gc = (lane & 3) * 2;
    float* red = (float*)sm;   // [4 wn][64 rows][2]

    // pass 1: v = acc + bias + R (overwrite acc), partial row sums
    #pragma unroll
    for (int mi = 0; mi < 2; mi++) {
        #pragma unroll
        for (int hrow = 0; hrow < 2; hrow++) {
            const int rl = wm * 32 + mi * 16 + hrow * 8 + gr;
            const int row = m0 + rl;
            float s = 0.f, ss = 0.f;
            #pragma unroll
            for (int ni = 0; ni < 8; ni++) {
                const int col = wn * 64 + ni * 8 + gc;
                float2 r2 = *(const float2*)(R + (size_t)row * N + col);
                float v0 = acc[mi][ni][2 * hrow + 0] + bias[col] + r2.x;
                float v1 = acc[mi][ni][2 * hrow + 1] + bias[col + 1] + r2.y;
                acc[mi][ni][2 * hrow + 0] = v0;
                acc[mi][ni][2 * hrow + 1] = v1;
                s += v0 + v1;
                ss += v0 * v0 + v1 * v1;
            }
            s  += __shfl_xor_sync(0xffffffffu, s, 1);
            s  += __shfl_xor_sync(0xffffffffu, s, 2);
            ss += __shfl_xor_sync(0xffffffffu, ss, 1);
            ss += __shfl_xor_sync(0xffffffffu, ss, 2);
            if ((lane & 3) == 0) {
                red[(wn * 64 + rl) * 2 + 0] = s;
                red[(wn * 64 + rl) * 2 + 1] = ss;
            }
        }
    }
    __syncthreads();

    // pass 2: combine across 4 wn warps, normalize, store
    #pragma unroll
    for (int mi = 0; mi < 2; mi++) {
        #pragma unroll
        for (int hrow = 0; hrow < 2; hrow++) {
            const int rl = wm * 32 + mi * 16 + hrow * 8 + gr;
            const int row = m0 + rl;
            float s = 0.f, ss = 0.f;
            #pragma unroll
            for (int w = 0; w < 4; w++) {
                s  += red[(w * 64 + rl) * 2 + 0];
                ss += red[(w * 64 + rl) * 2 + 1];
            }
            const float mean = s * (1.f / N);
            const float var  = ss * (1.f / N) - mean * mean;
            const float rstd = rsqrtf(var + LN_EPS);
            #pragma unroll
            for (int ni = 0; ni < 8; ni++) {
                const int col = wn * 64 + ni * 8 + gc;
                float y0 = (acc[mi][ni][2 * hrow + 0] - mean) * rstd * gamma[col] + beta[col];
                float y1 = (acc[mi][ni][2 * hrow + 1] - mean) * rstd * gamma[col + 1] + beta[col + 1];
                *(float2*)(Y + (size_t)row * N + col) = make_float2(y0, y1);
                if (OB) {
                    *(uint32_t*)(Yb + (size_t)row * N + col) =
                        ((uint32_t)b16(y1) << 16) | b16(y0);
                }
            }
        }
    }
}

// ---------------- deformable gather, vectorized ----------------
__global__ void __launch_bounds__(256) deform_kernel(
    const __nv_bfloat16* __restrict__ value,
    const float* __restrict__ off,
    const float* __restrict__ attnw,
    const float* __restrict__ ref,
    __nv_bfloat16* __restrict__ outb)
{
    const int q = blockIdx.x;
    const int n = q >> 14;
    const int h = threadIdx.x >> 5;
    const int lane = threadIdx.x & 31;
    const int half = lane >> 4;
    const int pl = lane & 15;

    const float* offp = off   + (size_t)q * 256 + h * 32;
    const float* awp  = attnw + (size_t)q * 128 + h * 16;
    const float* refp = ref   + (size_t)q * 8;

    float2 acc = make_float2(0.f, 0.f);
    #pragma unroll
    for (int l = 0; l < N_LEVELS; l++) {
        const float rx = refp[l * 2 + 0] * 128.f - 0.5f;
        const float ry = refp[l * 2 + 1] * 128.f - 0.5f;
        const __nv_bfloat16* vb =
            value + (((size_t)n * LIN + l * LQ) * N_HEADS + h) * HEAD_DIM + 2 * pl;
        #pragma unroll
        for (int p = 0; p < N_POINTS; p++) {
            const float x = rx + offp[l * 8 + p * 2 + 0];
            const float y = ry + offp[l * 8 + p * 2 + 1];
            const float aw = awp[l * 4 + p];
            const float xf = floorf(x), yf = floorf(y);
            const int x0 = (int)xf, y0 = (int)yf;
            const float wx = x - xf, wy = y - yf;

            const int xs = x0 + half;
            const float wxa = (half ? wx : 1.f - wx) * aw;
            const bool xok = (xs >= 0) && (xs < HW);
            const int xc = min(max(xs, 0), HW - 1);

            {
                const float w = (xok && y0 >= 0 && y0 < HW) ? wxa * (1.f - wy) : 0.f;
                const int yc = min(max(y0, 0), HW - 1);
                const uint32_t u = *(const uint32_t*)(vb + (size_t)(yc * HW + xc) * 256);
                acc.x = fmaf(w, __uint_as_float(u << 16), acc.x);
                acc.y = fmaf(w, __uint_as_float(u & 0xffff0000u), acc.y);
            }
            {
                const int y1 = y0 + 1;
                const float w = (xok && y1 >= 0 && y1 < HW) ? wxa * wy : 0.f;
                const int yc = min(max(y1, 0), HW - 1);
                const uint32_t u = *(const uint32_t*)(vb + (size_t)(yc * HW + xc) * 256);
                acc.x = fmaf(w, __uint_as_float(u << 16), acc.x);
                acc.y = fmaf(w, __uint_as_float(u & 0xffff0000u), acc.y);
            }
        }
    }
    acc.x += __shfl_xor_sync(0xffffffffu, acc.x, 16);
    acc.y += __shfl_xor_sync(0xffffffffu, acc.y, 16);
    if (half == 0) {
        *(uint32_t*)(outb + (size_t)q * 256 + h * 32 + 2 * pl) =
            ((uint32_t)b16(acc.y) << 16) | b16(acc.x);
    }
}

// ---------------- launch ----------------
extern "C" void kernel_launch(void* const* d_in, const int* in_sizes, int n_in,
                              void* d_out, int out_size)
{
    const float* cur_src = (const float*)d_in[0];
    const float* src_all = (const float*)d_in[1];
    const float* pos     = (const float*)d_in[2];
    const float* ref     = (const float*)d_in[3];
    const float* W_off   = (const float*)d_in[6];
    const float* b_off   = (const float*)d_in[7];
    const float* W_attn  = (const float*)d_in[8];
    const float* b_attn  = (const float*)d_in[9];
    const float* W_val   = (const float*)d_in[10];
    const float* b_val   = (const float*)d_in[11];
    const float* W_out   = (const float*)d_in[12];
    const float* b_out   = (const float*)d_in[13];
    const float* gamma1  = (const float*)d_in[14];
    const float* beta1   = (const float*)d_in[15];
    const float* W1      = (const float*)d_in[16];
    const float* b1      = (const float*)d_in[17];
    const float* W2      = (const float*)d_in[18];
    const float* b2      = (const float*)d_in[19];
    const float* gamma2  = (const float*)d_in[20];
    const float* beta2   = (const float*)d_in[21];
    float* out = (float*)d_out;

    float* scratch = nullptr;
    cudaGetSymbolAddress((void**)&scratch, g_scratch);
    float* offb = scratch + OFF_OFFB;
    float* attn = scratch + OFF_ATTN;
    float* src  = scratch + OFF_SRC;

    __nv_bfloat16* VALB= (__nv_bfloat16*)(scratch + OFF_VALUEB);
    __nv_bfloat16* QB  = (__nv_bfloat16*)(scratch + OFF_QB);
    __nv_bfloat16* AOB = (__nv_bfloat16*)(scratch + OFF_AOB);
    __nv_bfloat16* SRCB= (__nv_bfloat16*)(scratch + OFF_SRCB);
    __nv_bfloat16* HB  = (__nv_bfloat16*)(scratch + OFF_HB);
    __nv_bfloat16* WVH = (__nv_bfloat16*)(scratch + OFF_WVH);
    __nv_bfloat16* WVL = (__nv_bfloat16*)(scratch + OFF_WVL);
    __nv_bfloat16* WOH = (__nv_bfloat16*)(scratch + OFF_WOH);
    __nv_bfloat16* WOL = (__nv_bfloat16*)(scratch + OFF_WOL);
    __nv_bfloat16* WAH = (__nv_bfloat16*)(scratch + OFF_WAH);
    __nv_bfloat16* WAL = (__nv_bfloat16*)(scratch + OFF_WAL);
    __nv_bfloat16* WUH = (__nv_bfloat16*)(scratch + OFF_WUH);
    __nv_bfloat16* WUL = (__nv_bfloat16*)(scratch + OFF_WUL);
    __nv_bfloat16* W1H = (__nv_bfloat16*)(scratch + OFF_W1H);
    __nv_bfloat16* W1L = (__nv_bfloat16*)(scratch + OFF_W1L);
    __nv_bfloat16* W2H = (__nv_bfloat16*)(scratch + OFF_W2H);
    __nv_bfloat16* W2L = (__nv_bfloat16*)(scratch + OFF_W2L);

    const int SMEM3  = 2 * 3 * MATW * 2;       // split-B stages
    const int SMEM2  = 2 * 2 * MATW * 2;       // single-B stages
    const int SMEMLN = 2 * LN_STAGE_W * 2;     // gemm_ln stages

    cudaFuncSetAttribute((const void*)gemm2<0, 0, 1>,
                         cudaFuncAttributeMaxDynamicSharedMemorySize, SMEM3);
    cudaFuncSetAttribute((const void*)gemm2<3, 0, 1>,
                         cudaFuncAttributeMaxDynamicSharedMemorySize, SMEM3);
    cudaFuncSetAttribute((const void*)gemm2<1, 1, 0>,
                         cudaFuncAttributeMaxDynamicSharedMemorySize, SMEM2);
    cudaFuncSetAttribute((const void*)gemm_va,
                         cudaFuncAttributeMaxDynamicSharedMemorySize, SMEM2);
    cudaFuncSetAttribute((const void*)gemm_ln<true>,
                         cudaFuncAttributeMaxDynamicSharedMemorySize, SMEMLN);
    cudaFuncSetAttribute((const void*)gemm_ln<false>,
                         cudaFuncAttributeMaxDynamicSharedMemorySize, SMEMLN);

    // 0. merged weight transpose + split (1 launch)
    {
        WSJobs j;
        j.src[0] = W_val;  j.hi[0] = WVH; j.lo[0] = WVL; j.K[0] = 256;  j.N[0] = 256;
        j.src[1] = W_off;  j.hi[1] = WOH; j.lo[1] = WOL; j.K[1] = 256;  j.N[1] = 256;
        j.src[2] = W_attn; j.hi[2] = WAH; j.lo[2] = WAL; j.K[2] = 256;  j.N[2] = 128;
        j.src[3] = W_out;  j.hi[3] = WUH; j.lo[3] = WUL; j.K[3] = 256;  j.N[3] = 256;
        j.src[4] = W1;     j.hi[4] = W1H; j.lo[4] = W1L; j.K[4] = 256;  j.N[4] = 1024;
        j.src[5] = W2;     j.hi[5] = W2H; j.lo[5] = W2L; j.K[5] = 1024; j.N[5] = 256;
        int off = 0;
        for (int s = 0; s < 6; s++) { j.off[s] = off; off += j.K[s] * j.N[s]; }
        j.off[6] = off;
        wsplit_all_kernel<<<(off + 255) / 256, 256>>>(j);
    }

    // 0b. q = cur + pos[:,3] -> bf16
    q_cvt_kernel<<<(M_Q*64 + 255)/256, 256>>>(cur_src, pos, QB, M_Q * 64);

    // 1. value = (src_all + pos) @ W_val + b_val -> bf16 (fused add in A-staging)
    {
        dim3 grid(2, M_V / 128);
        gemm_va<<<grid, 256, SMEM2>>>(src_all, pos, WVH, b_val, VALB, M_V, 256, 256);
    }

    // 2. off = q @ W_off + b_off -> fp32 (split-B)
    {
        dim3 grid(2, M_Q / 128);
        gemm2<0, 0, 1><<<grid, 256, SMEM3>>>(
            QB, WOH, WOL, b_off, offb, nullptr, M_Q, 256, 256);
    }

    // 3. attn = softmax16( q @ W_attn + b_attn ), fused epilogue (split-B)
    {
        dim3 grid(1, M_Q / 128);
        gemm2<3, 0, 1><<<grid, 256, SMEM3>>>(
            QB, WAH, WAL, b_attn, attn, nullptr, M_Q, 128, 256);
    }

    // 4. deformable gather -> bf16 attnout
    deform_kernel<<<M_Q, 256>>>(VALB, offb, attn, ref, AOB);

    // 5. src = LN1( attnout @ W_out + b_out + cur_src )  (+ bf16 copy), fused
    gemm_ln<true><<<M_Q / 64, 256, SMEMLN>>>(
        AOB, WUH, b_out, cur_src, gamma1, beta1, src, SRCB, M_Q, 256);

    // 6. h = relu(src @ W1 + b1) -> bf16
    {
        dim3 grid(8, M_Q / 128);
        gemm2<1, 1, 0><<<grid, 256, SMEM2>>>(
            SRCB, W1H, nullptr, b1, nullptr, HB, M_Q, D_FFN, 256);
    }

    // 7. out = LN2( h @ W2 + b2 + src ), fused
    gemm_ln<false><<<M_Q / 64, 256, SMEMLN>>>(
        HB, W2H, b2, src, gamma2, beta2, out, nullptr, M_Q, 1024);
}

// round 15
// speedup vs baseline: 1.0511x; 1.0511x over previous
#include <cuda_runtime.h>
#include <cuda_bf16.h>
#include <cstdint>
#include <math.h>

// ---------------- problem constants ----------------
#define BATCH     2
#define HW        128
#define LQ        (HW*HW)          // 16384
#define N_LEVELS  4
#define LIN       (N_LEVELS*LQ)    // 65536
#define D_MODEL   256
#define N_HEADS   8
#define HEAD_DIM  32
#define N_POINTS  4
#define D_FFN     1024
#define LN_EPS    1e-5f

#define M_Q   (BATCH*LQ)           // 32768
#define M_V   (BATCH*LIN)          // 131072

// ---------------- scratch layout (in floats) ----------------
#define OFF_VAB     0            // (src_all+pos) bf16   M_V*256
#define OFF_VALUEB  16777216     // value bf16           M_V*256
#define OFF_QB      33554432     // q bf16               M_Q*256
#define OFF_OFFB    37748736     // off fp32             M_Q*256
#define OFF_ATTN    46137344     // attn fp32            M_Q*128
#define OFF_AOB     50331648     // attnout bf16         M_Q*256
#define OFF_SRC     54525952     // src fp32             M_Q*256
#define OFF_SRCB    62914560     // src bf16             M_Q*256
#define OFF_HB      67108864     // h bf16               M_Q*1024
#define OFF_WVH     83886080
#define OFF_WVL     83918848
#define OFF_WOH     83951616
#define OFF_WOL     83984384
#define OFF_WAH     84017152
#define OFF_WAL     84033536
#define OFF_WUH     84049920
#define OFF_WUL     84082688
#define OFF_W1H     84115456
#define OFF_W1L     84246528
#define OFF_W2H     84377600
#define OFF_W2L     84508672
#define SCRATCH_FLOATS 84639744

__device__ float g_scratch[SCRATCH_FLOATS];

// ---------------- helpers ----------------
__device__ __forceinline__ uint32_t smem_u32(const void* p) {
    uint32_t a;
    asm("{ .reg .u64 t; cvta.to.shared.u64 t, %1; cvt.u32.u64 %0, t; }" : "=r"(a) : "l"(p));
    return a;
}

__device__ __forceinline__ unsigned short b16(float x) {
    return __bfloat16_as_ushort(__float2bfloat16_rn(x));
}

__device__ __forceinline__ void ldm_x4(uint32_t* r, uint32_t addr) {
    asm volatile("ldmatrix.sync.aligned.m8n8.x4.shared.b16 {%0,%1,%2,%3}, [%4];"
        : "=r"(r[0]), "=r"(r[1]), "=r"(r[2]), "=r"(r[3]) : "r"(addr));
}

__device__ __forceinline__ void mma_bf16(float* c, const uint32_t* a, const uint32_t* b) {
    asm volatile(
        "mma.sync.aligned.m16n8k16.row.col.f32.bf16.bf16.f32 "
        "{%0,%1,%2,%3}, {%4,%5,%6,%7}, {%8,%9}, {%0,%1,%2,%3};"
        : "+f"(c[0]), "+f"(c[1]), "+f"(c[2]), "+f"(c[3])
        : "r"(a[0]), "r"(a[1]), "r"(a[2]), "r"(a[3]), "r"(b[0]), "r"(b[1]));
}

__device__ __forceinline__ void cp16(uint32_t dst, const void* src) {
    asm volatile("cp.async.cg.shared.global [%0], [%1], 16;" :: "r"(dst), "l"(src));
}
__device__ __forceinline__ void cp_commit() { asm volatile("cp.async.commit_group;"); }
template<int W> __device__ __forceinline__ void cp_wait() {
    asm volatile("cp.async.wait_group %0;" :: "n"(W));
}

#define SMPAD 40
#define MATW  (128 * SMPAD)

// ---------------- merged weight transpose + bf16 hi/lo split ----------------
struct WSJobs {
    const float* src[6];
    __nv_bfloat16* hi[6];
    __nv_bfloat16* lo[6];
    int K[6];
    int N[6];
    int off[7];
};

__global__ void wsplit_all_kernel(WSJobs jobs)
{
    int idx = blockIdx.x * blockDim.x + threadIdx.x;
    if (idx >= jobs.off[6]) return;
    #pragma unroll
    for (int s = 0; s < 6; s++) {
        if (idx >= jobs.off[s] && idx < jobs.off[s + 1]) {
            int local = idx - jobs.off[s];
            int N = jobs.N[s], K = jobs.K[s];
            int k = local / N, n = local - k * N;
            float x = jobs.src[s][local];
            __nv_bfloat16 h = __float2bfloat16_rn(x);
            __nv_bfloat16 l = __float2bfloat16_rn(x - __bfloat162float(h));
            jobs.hi[s][(size_t)n * K + k] = h;
            jobs.lo[s][(size_t)n * K + k] = l;
            return;
        }
    }
}

// ---------------- elementwise add -> single bf16 ----------------
__global__ void add_cvt_kernel(const float* __restrict__ a, const float* __restrict__ b,
                               __nv_bfloat16* __restrict__ o, int total4)
{
    int i = blockIdx.x * blockDim.x + threadIdx.x;
    if (i >= total4) return;
    float4 va = ((const float4*)a)[i];
    float4 vb = ((const float4*)b)[i];
    uint2 hp;
    hp.x = ((uint32_t)b16(va.y + vb.y) << 16) | b16(va.x + vb.x);
    hp.y = ((uint32_t)b16(va.w + vb.w) << 16) | b16(va.z + vb.z);
    ((uint2*)o)[i] = hp;
}

// ---------------- q = cur + pos[:,3] -> single bf16 ----------------
__global__ void q_cvt_kernel(const float* __restrict__ cur, const float* __restrict__ pos,
                             __nv_bfloat16* __restrict__ o, int total4)
{
    int i = blockIdx.x * blockDim.x + threadIdx.x;
    if (i >= total4) return;
    int idx = i * 4;
    int n = idx / (LQ * D_MODEL);
    int rem = idx - n * (LQ * D_MODEL);
    float4 va = *(const float4*)(cur + idx);
    float4 vb = *(const float4*)(pos + (size_t)(n * N_LEVELS + 3) * (LQ * D_MODEL) + rem);
    uint2 hp;
    hp.x = ((uint32_t)b16(va.y + vb.y) << 16) | b16(va.x + vb.x);
    hp.y = ((uint32_t)b16(va.w + vb.w) << 16) | b16(va.z + vb.z);
    ((uint2*)o)[i] = hp;
}

// ---------------- bf16 HMMA GEMM (optional B hi/lo split) ----------------
// CTA tile 128x128, BK=32, double-buffered cp.async, 8 warps (4m x 2n).
// EPI: 0=none 1=relu 3=softmax16.  OMODE: 0=fp32 C, 1=bf16 Cb.
template<int EPI, int OMODE, int BSPLIT>
__global__ void __launch_bounds__(256, 2) gemm2(
    const __nv_bfloat16* __restrict__ A,
    const __nv_bfloat16* __restrict__ Bhi, const __nv_bfloat16* __restrict__ Blo,
    const float* __restrict__ bias,
    float* __restrict__ C, __nv_bfloat16* __restrict__ Cb,
    int M, int N, int K)
{
    const int NMAT = BSPLIT ? 3 : 2;
    extern __shared__ unsigned short sm[];
    const int tid = threadIdx.x;
    const int wid = tid >> 5, lane = tid & 31;
    const int wm = wid & 3, wn = wid >> 2;
    const int m0 = blockIdx.y * 128, n0 = blockIdx.x * 128;
    const uint32_t smb = smem_u32(sm);

    const int a_r  = lane & 15;
    const int a_kb = (lane >> 4) * 16;
    const int b_r  = ((lane >> 4) & 1) * 8 + (lane & 7);
    const int b_kb = ((lane >> 3) & 1) * 16;

    const int row_l = tid >> 2;
    const int q4    = tid & 3;

    float acc[2][8][4];
    #pragma unroll
    for (int i = 0; i < 2; i++)
        #pragma unroll
        for (int j = 0; j < 8; j++)
            #pragma unroll
            for (int t = 0; t < 4; t++) acc[i][j][t] = 0.f;

    const int nchunks = K >> 5;

    auto stage_load = [&](int buf, int k0) {
        #pragma unroll
        for (int j = 0; j < 2 * NMAT; j++) {
            const int mat = j >> 1;
            const int row = (j & 1) * 64 + row_l;
            const __nv_bfloat16* base = (mat == 0) ? A : (mat == 1) ? Bhi : Blo;
            const int r0 = (mat == 0) ? m0 : n0;
            const __nv_bfloat16* src = base + (size_t)(r0 + row) * K + k0 + q4 * 8;
            const uint32_t dst = smb +
                (uint32_t)(((buf * NMAT + mat) * MATW + row * SMPAD + q4 * 8) * 2);
            cp16(dst, src);
        }
        cp_commit();
    };

    stage_load(0, 0);
    for (int i = 0; i < nchunks; i++) {
        if (i + 1 < nchunks) { stage_load((i + 1) & 1, (i + 1) << 5); cp_wait<1>(); }
        else                 { cp_wait<0>(); }
        __syncthreads();

        const uint32_t sb  = smb + (uint32_t)((i & 1) * NMAT * MATW * 2);
        const uint32_t AB  = sb;
        const uint32_t BhB = sb + MATW * 2, BlB = sb + 2 * MATW * 2;

        #pragma unroll
        for (int ks2 = 0; ks2 <= 32; ks2 += 32) {
            uint32_t ar[2][4];
            #pragma unroll
            for (int mi = 0; mi < 2; mi++) {
                const uint32_t ao = (uint32_t)((wm * 32 + mi * 16 + a_r) * (SMPAD * 2)) + a_kb + ks2;
                ldm_x4(ar[mi], AB + ao);
            }
            #pragma unroll
            for (int nc = 0; nc < 4; nc++) {
                uint32_t bh[4], bl[4];
                const uint32_t bo = (uint32_t)((wn * 64 + nc * 16 + b_r) * (SMPAD * 2)) + b_kb + ks2;
                ldm_x4(bh, BhB + bo);
                if (BSPLIT) ldm_x4(bl, BlB + bo);
                #pragma unroll
                for (int mi = 0; mi < 2; mi++) {
                    #pragma unroll
                    for (int s = 0; s < 2; s++) {
                        float* c = acc[mi][nc * 2 + s];
                        mma_bf16(c, ar[mi], bh + s * 2);
                        if (BSPLIT) mma_bf16(c, ar[mi], bl + s * 2);
                    }
                }
            }
        }
        __syncthreads();
    }

    const int gr = lane >> 2, gc = (lane & 3) * 2;

    if (EPI == 3) {
        #pragma unroll
        for (int mi = 0; mi < 2; mi++) {
            #pragma unroll
            for (int hrow = 0; hrow < 2; hrow++) {
                const int row = m0 + wm * 32 + mi * 16 + gr + hrow * 8;
                #pragma unroll
                for (int g = 0; g < 4; g++) {
                    const int c0 = n0 + wn * 64 + g * 16;
                    float a0 = acc[mi][2*g  ][2*hrow + 0] + bias[c0 + gc];
                    float a1 = acc[mi][2*g  ][2*hrow + 1] + bias[c0 + gc + 1];
                    float b0 = acc[mi][2*g+1][2*hrow + 0] + bias[c0 + 8 + gc];
                    float b1 = acc[mi][2*g+1][2*hrow + 1] + bias[c0 + 8 + gc + 1];
                    float mx = fmaxf(fmaxf(a0, a1), fmaxf(b0, b1));
                    mx = fmaxf(mx, __shfl_xor_sync(0xffffffffu, mx, 1));
                    mx = fmaxf(mx, __shfl_xor_sync(0xffffffffu, mx, 2));
                    a0 = __expf(a0 - mx); a1 = __expf(a1 - mx);
                    b0 = __expf(b0 - mx); b1 = __expf(b1 - mx);
                    float s = a0 + a1 + b0 + b1;
                    s += __shfl_xor_sync(0xffffffffu, s, 1);
                    s += __shfl_xor_sync(0xffffffffu, s, 2);
                    const float inv = 1.f / s;
                    *(float2*)(C + (size_t)row * N + c0 + gc)     = make_float2(a0 * inv, a1 * inv);
                    *(float2*)(C + (size_t)row * N + c0 + 8 + gc) = make_float2(b0 * inv, b1 * inv);
                }
            }
        }
        return;
    }

    #pragma unroll
    for (int mi = 0; mi < 2; mi++) {
        const int row = m0 + wm * 32 + mi * 16 + gr;
        #pragma unroll
        for (int ni = 0; ni < 8; ni++) {
            const int col = n0 + wn * 64 + ni * 8 + gc;
            const float b0 = bias[col], b1 = bias[col + 1];
            float2 v0, v1;
            v0.x = acc[mi][ni][0] + b0; v0.y = acc[mi][ni][1] + b1;
            v1.x = acc[mi][ni][2] + b0; v1.y = acc[mi][ni][3] + b1;
            if (EPI == 1) {
                v0.x = fmaxf(v0.x, 0.f); v0.y = fmaxf(v0.y, 0.f);
                v1.x = fmaxf(v1.x, 0.f); v1.y = fmaxf(v1.y, 0.f);
            }
            if (OMODE == 1) {
                *(uint32_t*)(Cb + (size_t)row * N + col) =
                    ((uint32_t)b16(v0.y) << 16) | b16(v0.x);
                *(uint32_t*)(Cb + (size_t)(row + 8) * N + col) =
                    ((uint32_t)b16(v1.y) << 16) | b16(v1.x);
            } else {
                *(float2*)(C + (size_t)row * N + col) = v0;
                *(float2*)(C + (size_t)(row + 8) * N + col) = v1;
            }
        }
    }
}

// ---------------- GEMM with fused bias+residual+LayerNorm epilogue ----------------
// BM=64, BN=256(=N), BK=32; 8 warps as 2m x 4n (warp tile 32x64).
// Y = LN(A @ B^T + bias + R); optional bf16 copy Yb.
#define LN_STAGE_ROWS 320
#define LN_STAGE_W   (LN_STAGE_ROWS * SMPAD)

template<bool OB>
__global__ void __launch_bounds__(256, 2) gemm_ln(
    const __nv_bfloat16* __restrict__ A, const __nv_bfloat16* __restrict__ B,
    const float* __restrict__ bias, const float* __restrict__ R,
    const float* __restrict__ gamma, const float* __restrict__ beta,
    float* __restrict__ Y, __nv_bfloat16* __restrict__ Yb,
    int M, int K)
{
    const int N = 256;
    extern __shared__ unsigned short sm[];
    const int tid = threadIdx.x;
    const int wid = tid >> 5, lane = tid & 31;
    const int wm = wid & 1, wn = wid >> 1;        // 2m x 4n
    const int m0 = blockIdx.x * 64;
    const uint32_t smb = smem_u32(sm);

    const int a_r  = lane & 15;
    const int a_kb = (lane >> 4) * 16;
    const int b_r  = ((lane >> 4) & 1) * 8 + (lane & 7);
    const int b_kb = ((lane >> 3) & 1) * 16;

    float acc[2][8][4];
    #pragma unroll
    for (int i = 0; i < 2; i++)
        #pragma unroll
        for (int j = 0; j < 8; j++)
            #pragma unroll
            for (int t = 0; t < 4; t++) acc[i][j][t] = 0.f;

    const int nchunks = K >> 5;

    auto stage_load = [&](int buf, int k0) {
        #pragma unroll
        for (int j = 0; j < 5; j++) {
            const int c = tid + j * 256;          // 0..1279
            const int row = c >> 2, q4c = c & 3;
            const __nv_bfloat16* src = (row < 64)
                ? A + (size_t)(m0 + row) * K + k0 + q4c * 8
                : B + (size_t)(row - 64) * K + k0 + q4c * 8;
            const uint32_t dst = smb +
                (uint32_t)((buf * LN_STAGE_W + row * SMPAD + q4c * 8) * 2);
            cp16(dst, src);
        }
        cp_commit();
    };

    stage_load(0, 0);
    for (int i = 0; i < nchunks; i++) {
        if (i + 1 < nchunks) { stage_load((i + 1) & 1, (i + 1) << 5); cp_wait<1>(); }
        else                 { cp_wait<0>(); }
        __syncthreads();

        const uint32_t sb = smb + (uint32_t)((i & 1) * LN_STAGE_W * 2);
        const uint32_t AB = sb;
        const uint32_t BB = sb + 64 * SMPAD * 2;

        #pragma unroll
        for (int ks2 = 0; ks2 <= 32; ks2 += 32) {
            uint32_t ar[2][4];
            #pragma unroll
            for (int mi = 0; mi < 2; mi++) {
                const uint32_t ao = (uint32_t)((wm * 32 + mi * 16 + a_r) * (SMPAD * 2)) + a_kb + ks2;
                ldm_x4(ar[mi], AB + ao);
            }
            #pragma unroll
            for (int nc = 0; nc < 4; nc++) {
                uint32_t bh[4];
                const uint32_t bo = (uint32_t)((wn * 64 + nc * 16 + b_r) * (SMPAD * 2)) + b_kb + ks2;
                ldm_x4(bh, BB + bo);
                #pragma unroll
                for (int mi = 0; mi < 2; mi++) {
                    #pragma unroll
                    for (int s = 0; s < 2; s++)
                        mma_bf16(acc[mi][nc * 2 + s], ar[mi], bh + s * 2);
                }
            }
        }
        __syncthreads();
    }

    // ---- fused bias + residual + LayerNorm epilogue ----
    const int gr = lane >> 2, gc = (lane & 3) * 2;
    float* red = (float*)sm;   // [4 wn][64 rows][2]

    #pragma unroll
    for (int mi = 0; mi < 2; mi++) {
        #pragma unroll
        for (int hrow = 0; hrow < 2; hrow++) {
            const int rl = wm * 32 + mi * 16 + hrow * 8 + gr;
            const int row = m0 + rl;
            float s = 0.f, ss = 0.f;
            #pragma unroll
            for (int ni = 0; ni < 8; ni++) {
                const int col = wn * 64 + ni * 8 + gc;
                float2 r2 = *(const float2*)(R + (size_t)row * N + col);
                float v0 = acc[mi][ni][2 * hrow + 0] + bias[col] + r2.x;
                float v1 = acc[mi][ni][2 * hrow + 1] + bias[col + 1] + r2.y;
                acc[mi][ni][2 * hrow + 0] = v0;
                acc[mi][ni][2 * hrow + 1] = v1;
                s += v0 + v1;
                ss += v0 * v0 + v1 * v1;
            }
            s  += __shfl_xor_sync(0xffffffffu, s, 1);
            s  += __shfl_xor_sync(0xffffffffu, s, 2);
            ss += __shfl_xor_sync(0xffffffffu, ss, 1);
            ss += __shfl_xor_sync(0xffffffffu, ss, 2);
            if ((lane & 3) == 0) {
                red[(wn * 64 + rl) * 2 + 0] = s;
                red[(wn * 64 + rl) * 2 + 1] = ss;
            }
        }
    }
    __syncthreads();

    #pragma unroll
    for (int mi = 0; mi < 2; mi++) {
        #pragma unroll
        for (int hrow = 0; hrow < 2; hrow++) {
            const int rl = wm * 32 + mi * 16 + hrow * 8 + gr;
            const int row = m0 + rl;
            float s = 0.f, ss = 0.f;
            #pragma unroll
            for (int w = 0; w < 4; w++) {
                s  += red[(w * 64 + rl) * 2 + 0];
                ss += red[(w * 64 + rl) * 2 + 1];
            }
            const float mean = s * (1.f / N);
            const float var  = ss * (1.f / N) - mean * mean;
            const float rstd = rsqrtf(var + LN_EPS);
            #pragma unroll
            for (int ni = 0; ni < 8; ni++) {
                const int col = wn * 64 + ni * 8 + gc;
                float y0 = (acc[mi][ni][2 * hrow + 0] - mean) * rstd * gamma[col] + beta[col];
                float y1 = (acc[mi][ni][2 * hrow + 1] - mean) * rstd * gamma[col + 1] + beta[col + 1];
                *(float2*)(Y + (size_t)row * N + col) = make_float2(y0, y1);
                if (OB) {
                    *(uint32_t*)(Yb + (size_t)row * N + col) =
                        ((uint32_t)b16(y1) << 16) | b16(y0);
                }
            }
        }
    }
}

// ---------------- deformable gather, vectorized ----------------
__global__ void __launch_bounds__(256) deform_kernel(
    const __nv_bfloat16* __restrict__ value,
    const float* __restrict__ off,
    const float* __restrict__ attnw,
    const float* __restrict__ ref,
    __nv_bfloat16* __restrict__ outb)
{
    const int q = blockIdx.x;
    const int n = q >> 14;
    const int h = threadIdx.x >> 5;
    const int lane = threadIdx.x & 31;
    const int half = lane >> 4;
    const int pl = lane & 15;

    const float* offp = off   + (size_t)q * 256 + h * 32;
    const float* awp  = attnw + (size_t)q * 128 + h * 16;
    const float* refp = ref   + (size_t)q * 8;

    float2 acc = make_float2(0.f, 0.f);
    #pragma unroll
    for (int l = 0; l < N_LEVELS; l++) {
        const float rx = refp[l * 2 + 0] * 128.f - 0.5f;
        const float ry = refp[l * 2 + 1] * 128.f - 0.5f;
        const __nv_bfloat16* vb =
            value + (((size_t)n * LIN + l * LQ) * N_HEADS + h) * HEAD_DIM + 2 * pl;
        #pragma unroll
        for (int p = 0; p < N_POINTS; p++) {
            const float x = rx + offp[l * 8 + p * 2 + 0];
            const float y = ry + offp[l * 8 + p * 2 + 1];
            const float aw = awp[l * 4 + p];
            const float xf = floorf(x), yf = floorf(y);
            const int x0 = (int)xf, y0 = (int)yf;
            const float wx = x - xf, wy = y - yf;

            const int xs = x0 + half;
            const float wxa = (half ? wx : 1.f - wx) * aw;
            const bool xok = (xs >= 0) && (xs < HW);
            const int xc = min(max(xs, 0), HW - 1);

            {
                const float w = (xok && y0 >= 0 && y0 < HW) ? wxa * (1.f - wy) : 0.f;
                const int yc = min(max(y0, 0), HW - 1);
                const uint32_t u = *(const uint32_t*)(vb + (size_t)(yc * HW + xc) * 256);
                acc.x = fmaf(w, __uint_as_float(u << 16), acc.x);
                acc.y = fmaf(w, __uint_as_float(u & 0xffff0000u), acc.y);
            }
            {
                const int y1 = y0 + 1;
                const float w = (xok && y1 >= 0 && y1 < HW) ? wxa * wy : 0.f;
                const int yc = min(max(y1, 0), HW - 1);
                const uint32_t u = *(const uint32_t*)(vb + (size_t)(yc * HW + xc) * 256);
                acc.x = fmaf(w, __uint_as_float(u << 16), acc.x);
                acc.y = fmaf(w, __uint_as_float(u & 0xffff0000u), acc.y);
            }
        }
    }
    acc.x += __shfl_xor_sync(0xffffffffu, acc.x, 16);
    acc.y += __shfl_xor_sync(0xffffffffu, acc.y, 16);
    if (half == 0) {
        *(uint32_t*)(outb + (size_t)q * 256 + h * 32 + 2 * pl) =
            ((uint32_t)b16(acc.y) << 16) | b16(acc.x);
    }
}

// ---------------- launch ----------------
extern "C" void kernel_launch(void* const* d_in, const int* in_sizes, int n_in,
                              void* d_out, int out_size)
{
    const float* cur_src = (const float*)d_in[0];
    const float* src_all = (const float*)d_in[1];
    const float* pos     = (const float*)d_in[2];
    const float* ref     = (const float*)d_in[3];
    const float* W_off   = (const float*)d_in[6];
    const float* b_off   = (const float*)d_in[7];
    const float* W_attn  = (const float*)d_in[8];
    const float* b_attn  = (const float*)d_in[9];
    const float* W_val   = (const float*)d_in[10];
    const float* b_val   = (const float*)d_in[11];
    const float* W_out   = (const float*)d_in[12];
    const float* b_out   = (const float*)d_in[13];
    const float* gamma1  = (const float*)d_in[14];
    const float* beta1   = (const float*)d_in[15];
    const float* W1      = (const float*)d_in[16];
    const float* b1      = (const float*)d_in[17];
    const float* W2      = (const float*)d_in[18];
    const float* b2      = (const float*)d_in[19];
    const float* gamma2  = (const float*)d_in[20];
    const float* beta2   = (const float*)d_in[21];
    float* out = (float*)d_out;

    float* scratch = nullptr;
    cudaGetSymbolAddress((void**)&scratch, g_scratch);
    float* offb = scratch + OFF_OFFB;
    float* attn = scratch + OFF_ATTN;
    float* src  = scratch + OFF_SRC;

    __nv_bfloat16* VAB = (__nv_bfloat16*)(scratch + OFF_VAB);
    __nv_bfloat16* VALB= (__nv_bfloat16*)(scratch + OFF_VALUEB);
    __nv_bfloat16* QB  = (__nv_bfloat16*)(scratch + OFF_QB);
    __nv_bfloat16* AOB = (__nv_bfloat16*)(scratch + OFF_AOB);
    __nv_bfloat16* SRCB= (__nv_bfloat16*)(scratch + OFF_SRCB);
    __nv_bfloat16* HB  = (__nv_bfloat16*)(scratch + OFF_HB);
    __nv_bfloat16* WVH = (__nv_bfloat16*)(scratch + OFF_WVH);
    __nv_bfloat16* WVL = (__nv_bfloat16*)(scratch + OFF_WVL);
    __nv_bfloat16* WOH = (__nv_bfloat16*)(scratch + OFF_WOH);
    __nv_bfloat16* WOL = (__nv_bfloat16*)(scratch + OFF_WOL);
    __nv_bfloat16* WAH = (__nv_bfloat16*)(scratch + OFF_WAH);
    __nv_bfloat16* WAL = (__nv_bfloat16*)(scratch + OFF_WAL);
    __nv_bfloat16* WUH = (__nv_bfloat16*)(scratch + OFF_WUH);
    __nv_bfloat16* WUL = (__nv_bfloat16*)(scratch + OFF_WUL);
    __nv_bfloat16* W1H = (__nv_bfloat16*)(scratch + OFF_W1H);
    __nv_bfloat16* W1L = (__nv_bfloat16*)(scratch + OFF_W1L);
    __nv_bfloat16* W2H = (__nv_bfloat16*)(scratch + OFF_W2H);
    __nv_bfloat16* W2L = (__nv_bfloat16*)(scratch + OFF_W2L);

    const int SMEM3  = 2 * 3 * MATW * 2;       // split-B stages
    const int SMEM2  = 2 * 2 * MATW * 2;       // single-B stages
    const int SMEMLN = 2 * LN_STAGE_W * 2;     // gemm_ln stages

    cudaFuncSetAttribute((const void*)gemm2<0, 0, 1>,
                         cudaFuncAttributeMaxDynamicSharedMemorySize, SMEM3);
    cudaFuncSetAttribute((const void*)gemm2<3, 0, 1>,
                         cudaFuncAttributeMaxDynamicSharedMemorySize, SMEM3);
    cudaFuncSetAttribute((const void*)gemm2<0, 1, 0>,
                         cudaFuncAttributeMaxDynamicSharedMemorySize, SMEM2);
    cudaFuncSetAttribute((const void*)gemm2<1, 1, 0>,
                         cudaFuncAttributeMaxDynamicSharedMemorySize, SMEM2);
    cudaFuncSetAttribute((const void*)gemm_ln<true>,
                         cudaFuncAttributeMaxDynamicSharedMemorySize, SMEMLN);
    cudaFuncSetAttribute((const void*)gemm_ln<false>,
                         cudaFuncAttributeMaxDynamicSharedMemorySize, SMEMLN);

    // 0. merged weight transpose + split (1 launch)
    {
        WSJobs j;
        j.src[0] = W_val;  j.hi[0] = WVH; j.lo[0] = WVL; j.K[0] = 256;  j.N[0] = 256;
        j.src[1] = W_off;  j.hi[1] = WOH; j.lo[1] = WOL; j.K[1] = 256;  j.N[1] = 256;
        j.src[2] = W_attn; j.hi[2] = WAH; j.lo[2] = WAL; j.K[2] = 256;  j.N[2] = 128;
        j.src[3] = W_out;  j.hi[3] = WUH; j.lo[3] = WUL; j.K[3] = 256;  j.N[3] = 256;
        j.src[4] = W1;     j.hi[4] = W1H; j.lo[4] = W1L; j.K[4] = 256;  j.N[4] = 1024;
        j.src[5] = W2;     j.hi[5] = W2H; j.lo[5] = W2L; j.K[5] = 1024; j.N[5] = 256;
        int off = 0;
        for (int s = 0; s < 6; s++) { j.off[s] = off; off += j.K[s] * j.N[s]; }
        j.off[6] = off;
        wsplit_all_kernel<<<(off + 255) / 256, 256>>>(j);
    }

    // 0b. activation converts
    add_cvt_kernel<<<(M_V*64 + 255)/256, 256>>>(src_all, pos, VAB, M_V * 64);
    q_cvt_kernel<<<(M_Q*64 + 255)/256, 256>>>(cur_src, pos, QB, M_Q * 64);

    // 1. value = (src_all + pos) @ W_val + b_val -> bf16 (single-B)
    {
        dim3 grid(2, M_V / 128);
        gemm2<0, 1, 0><<<grid, 256, SMEM2>>>(
            VAB, WVH, nullptr, b_val, nullptr, VALB, M_V, 256, 256);
    }

    // 2. off = q @ W_off + b_off -> fp32 (split-B)
    {
        dim3 grid(2, M_Q / 128);
        gemm2<0, 0, 1><<<grid, 256, SMEM3>>>(
            QB, WOH, WOL, b_off, offb, nullptr, M_Q, 256, 256);
    }

    // 3. attn = softmax16( q @ W_attn + b_attn ), fused epilogue (split-B)
    {
        dim3 grid(1, M_Q / 128);
        gemm2<3, 0, 1><<<grid, 256, SMEM3>>>(
            QB, WAH, WAL, b_attn, attn, nullptr, M_Q, 128, 256);
    }

    // 4. deformable gather -> bf16 attnout
    deform_kernel<<<M_Q, 256>>>(VALB, offb, attn, ref, AOB);

    // 5. src = LN1( attnout @ W_out + b_out + cur_src )  (+ bf16 copy), fused
    gemm_ln<true><<<M_Q / 64, 256, SMEMLN>>>(
        AOB, WUH, b_out, cur_src, gamma1, beta1, src, SRCB, M_Q, 256);

    // 6. h = relu(src @ W1 + b1) -> bf16
    {
        dim3 grid(8, M_Q / 128);
        gemm2<1, 1, 0><<<grid, 256, SMEM2>>>(
            SRCB, W1H, nullptr, b1, nullptr, HB, M_Q, D_FFN, 256);
    }

    // 7. out = LN2( h @ W2 + b2 + src ), fused
    gemm_ln<false><<<M_Q / 64, 256, SMEMLN>>>(
        HB, W2H, b2, src, gamma2, beta2, out, nullptr, M_Q, 1024);
}